// round 1
// baseline (speedup 1.0000x reference)
#include <cuda_runtime.h>
#include <cuda_bf16.h>
#include <math.h>

#define BS 32
#define NQ 900
#define NC 91
#define NT 30
#define NTT (BS * NT)   // 960 total targets (columns of C)

// Transposed per-batch cost slice: g_slice[b][t][q] = C[b, q, b*NT + t]
__device__ float g_slice[BS * NT * NQ];

// ---------------------------------------------------------------------------
// Cost matrix: one block per (b,q) row. 128 threads.
// ---------------------------------------------------------------------------
__global__ __launch_bounds__(128) void cost_kernel(
    const float* __restrict__ logits,   // (BS, NQ, NC)
    const float* __restrict__ boxes,    // (BS, NQ, 4) cxcywh
    const int*   __restrict__ labels,   // (BS, NT)
    const float* __restrict__ tboxes,   // (BS, NT, 4) cxcywh
    float* __restrict__ C)              // (BS*NQ, NTT)
{
    const int row = blockIdx.x;         // 0 .. BS*NQ-1
    const int b   = row / NQ;
    const int q   = row - b * NQ;
    const int tid = threadIdx.x;

    __shared__ float prob[NC];
    __shared__ float red[128];
    __shared__ float s_scalar;

    // --- softmax over 91 classes for this row ---
    float l = (tid < NC) ? logits[(size_t)row * NC + tid] : -INFINITY;
    red[tid] = l;
    __syncthreads();
    for (int s = 64; s > 0; s >>= 1) {
        if (tid < s) red[tid] = fmaxf(red[tid], red[tid + s]);
        __syncthreads();
    }
    float smax = red[0];
    __syncthreads();
    float e = (tid < NC) ? expf(l - smax) : 0.0f;
    red[tid] = e;
    __syncthreads();
    for (int s = 64; s > 0; s >>= 1) {
        if (tid < s) red[tid] += red[tid + s];
        __syncthreads();
    }
    float ssum = red[0];
    if (tid < NC) prob[tid] = e / ssum;

    // --- own box ---
    if (tid == 0) s_scalar = 0.0f;  // dummy to keep structure
    __shared__ float4 sbox;
    if (tid == 0) sbox = reinterpret_cast<const float4*>(boxes)[row];
    __syncthreads();

    const float cx = sbox.x, cy = sbox.y, w = sbox.z, h = sbox.w;
    const float ax0 = cx - 0.5f * w, ay0 = cy - 0.5f * h;
    const float ax1 = cx + 0.5f * w, ay1 = cy + 0.5f * h;
    const float areaA = (ax1 - ax0) * (ay1 - ay0);

    // --- stream all 960 target columns ---
    for (int j = tid; j < NTT; j += 128) {
        const int lab = labels[j];
        const float4 tb = reinterpret_cast<const float4*>(tboxes)[j];

        const float cost_class = 1.0f - prob[lab];
        const float l1 = fabsf(cx - tb.x) + fabsf(cy - tb.y)
                       + fabsf(w - tb.z) + fabsf(h - tb.w);

        const float bx0 = tb.x - 0.5f * tb.z, by0 = tb.y - 0.5f * tb.w;
        const float bx1 = tb.x + 0.5f * tb.z, by1 = tb.y + 0.5f * tb.w;
        const float areaB = (bx1 - bx0) * (by1 - by0);

        const float ix0 = fmaxf(ax0, bx0), iy0 = fmaxf(ay0, by0);
        const float ix1 = fminf(ax1, bx1), iy1 = fminf(ay1, by1);
        const float iw = fmaxf(ix1 - ix0, 0.0f), ih = fmaxf(iy1 - iy0, 0.0f);
        const float inter = iw * ih;
        const float uni = areaA + areaB - inter;
        const float iou = inter / uni;

        const float ex0 = fminf(ax0, bx0), ey0 = fminf(ay0, by0);
        const float ex1 = fmaxf(ax1, bx1), ey1 = fmaxf(ay1, by1);
        const float ew = fmaxf(ex1 - ex0, 0.0f), eh = fmaxf(ey1 - ey0, 0.0f);
        const float encl = ew * eh;
        const float giou = iou - (encl - uni) / encl;

        const float c = 5.0f * l1 + 1.0f * cost_class + 2.0f * (1.0f - giou);
        C[(size_t)row * NTT + j] = c;

        // scatter own-batch columns into transposed slice for the LSA pass
        if (j >= b * NT && j < b * NT + NT) {
            const int t = j - b * NT;
            g_slice[((size_t)b * NT + t) * NQ + q] = c;
        }
    }
    (void)s_scalar;
}

// ---------------------------------------------------------------------------
// JV Hungarian (exact replica of the numpy reference) — one block per batch.
// cost is g_slice[b]: rows = targets (n=30), cols = queries (m=900), float64 math.
// ---------------------------------------------------------------------------
#define LSA_NTH 128

__global__ __launch_bounds__(LSA_NTH) void lsa_kernel(
    float* __restrict__ outPred,   // (BS, NT) as float
    float* __restrict__ outTgt)    // (BS, NT) as float
{
    const int b = blockIdx.x;
    const int tid = threadIdx.x;
    const float* __restrict__ cost = g_slice + (size_t)b * NT * NQ;

    const double DINF = 1e18;

    __shared__ double u[NT + 1];
    __shared__ double v[NQ + 1];
    __shared__ double minv[NQ + 1];
    __shared__ int way[NQ + 1];
    __shared__ int p[NQ + 1];
    __shared__ unsigned char used[NQ + 1];
    __shared__ double rv[LSA_NTH];
    __shared__ int ri[LSA_NTH];
    __shared__ int s_j0, s_i0;

    for (int j = tid; j <= NQ; j += LSA_NTH) { v[j] = 0.0; p[j] = 0; way[j] = 0; }
    if (tid <= NT) u[tid] = 0.0;
    __syncthreads();

    for (int i = 1; i <= NT; i++) {
        if (tid == 0) { p[0] = i; s_j0 = 0; }
        for (int j = tid; j <= NQ; j += LSA_NTH) { minv[j] = DINF; used[j] = 0; }
        __syncthreads();

        while (true) {
            if (tid == 0) { used[s_j0] = 1; s_i0 = p[s_j0]; }
            __syncthreads();
            const int j0 = s_j0;
            const int i0 = s_i0;
            const double ui0 = u[i0];
            const float* crow = cost + (size_t)(i0 - 1) * NQ;

            // update minv for unused columns; track per-thread argmin of minv
            double bv = DINF;
            int bi = NQ + 1;
            for (int j = 1 + tid; j <= NQ; j += LSA_NTH) {
                if (!used[j]) {
                    const double cur = (double)crow[j - 1] - ui0 - v[j];
                    double mv = minv[j];
                    if (cur < mv) { mv = cur; minv[j] = cur; way[j] = j0; }
                    if (mv < bv) { bv = mv; bi = j; }   // strict < keeps lowest j in-thread
                }
            }
            rv[tid] = bv; ri[tid] = bi;
            __syncthreads();
            for (int s = LSA_NTH / 2; s > 0; s >>= 1) {
                if (tid < s) {
                    if (rv[tid + s] < rv[tid] ||
                        (rv[tid + s] == rv[tid] && ri[tid + s] < ri[tid])) {
                        rv[tid] = rv[tid + s];
                        ri[tid] = ri[tid + s];
                    }
                }
                __syncthreads();
            }
            const double delta = rv[0];
            const int j1 = ri[0];
            __syncthreads();

            // dual update + minv shift. p[] distinct over used columns -> race-free.
            for (int j = tid; j <= NQ; j += LSA_NTH) {
                if (used[j]) { u[p[j]] += delta; v[j] -= delta; }
                else         { minv[j] -= delta; }
            }
            __syncthreads();

            const bool done = (p[j1] == 0);
            if (tid == 0) s_j0 = j1;
            __syncthreads();
            if (done) break;
        }

        // augment along alternating path (serial, thread 0)
        if (tid == 0) {
            int j0 = s_j0;
            while (j0) {
                const int j1 = way[j0];
                p[j0] = p[j1];
                j0 = j1;
            }
        }
        __syncthreads();
    }

    // extract assignment, stable argsort by pred index (distinct -> plain sort)
    if (tid == 0) {
        int preds[NT];
        for (int j = 1; j <= NQ; j++)
            if (p[j] > 0) preds[p[j] - 1] = j - 1;

        int order[NT];
        for (int k = 0; k < NT; k++) order[k] = k;
        for (int a = 1; a < NT; a++) {
            const int o = order[a];
            const int key = preds[o];
            int c = a - 1;
            while (c >= 0 && preds[order[c]] > key) { order[c + 1] = order[c]; c--; }
            order[c + 1] = o;
        }
        for (int k = 0; k < NT; k++) {
            outPred[b * NT + k] = (float)preds[order[k]];
            outTgt[b * NT + k] = (float)order[k];
        }
    }
}

// ---------------------------------------------------------------------------
extern "C" void kernel_launch(void* const* d_in, const int* in_sizes, int n_in,
                              void* d_out, int out_size)
{
    const float* logits = (const float*)d_in[0];   // (32,900,91) f32
    const float* boxes  = (const float*)d_in[1];   // (32,900,4)  f32
    const int*   labels = (const int*)d_in[2];     // (32,30)     i32
    const float* tboxes = (const float*)d_in[3];   // (32,30,4)   f32

    float* out = (float*)d_out;
    float* outC    = out;                                  // 32*900*960 elems
    float* outPred = out + (size_t)BS * NQ * NTT;          // 960 elems
    float* outTgt  = outPred + BS * NT;                    // 960 elems

    cost_kernel<<<BS * NQ, 128>>>(logits, boxes, labels, tboxes, outC);
    lsa_kernel<<<BS, LSA_NTH>>>(outPred, outTgt);
}